// round 9
// baseline (speedup 1.0000x reference)
#include <cuda_runtime.h>
#include <cuda_bf16.h>
#include <cstdint>

#define EPSF   1e-6f
#define TMAXF  0.999f

// ---------- small float3 helpers ----------
__device__ __forceinline__ float3 f3(float x, float y, float z) { return make_float3(x, y, z); }
__device__ __forceinline__ float3 f3sub(float3 a, float3 b) { return f3(a.x - b.x, a.y - b.y, a.z - b.z); }
__device__ __forceinline__ float3 f3add(float3 a, float3 b) { return f3(a.x + b.x, a.y + b.y, a.z + b.z); }
__device__ __forceinline__ float3 f3scale(float s, float3 a) { return f3(s * a.x, s * a.y, s * a.z); }
__device__ __forceinline__ float  dot3(float3 a, float3 b) { return a.x * b.x + a.y * b.y + a.z * b.z; }
__device__ __forceinline__ float3 cross3(float3 a, float3 b) {
    return f3(a.y * b.z - a.z * b.y,
              a.z * b.x - a.x * b.z,
              a.x * b.y - a.y * b.x);
}
__device__ __forceinline__ float3 ldg3(const float* __restrict__ p) {
    return f3(p[0], p[1], p[2]);
}

// triangles_contain (reference formula, fp32)
__device__ __forceinline__ bool tri_contains(float3 v0, float3 v1, float3 v2, float3 p) {
    float3 m0 = cross3(f3sub(p, v0), f3sub(v1, v0));
    float3 m1 = cross3(f3sub(p, v1), f3sub(v2, v1));
    float3 m2 = cross3(f3sub(p, v2), f3sub(v0, v2));
    float d01 = dot3(m0, m1);
    float d12 = dot3(m1, m2);
    float d20 = dot3(m2, m0);
    bool pos = (d01 >= 0.0f) && (d12 >= 0.0f) && (d20 >= 0.0f);
    bool neg = (d01 <= 0.0f) && (d12 <= 0.0f) && (d20 <= 0.0f);
    return pos || neg;
}

#define BLOCK 128

// Phase A: one THREAD per candidate computes the image-method path + masks.
// Survivors are compacted into a per-block shared queue.
// Phase B: block's warps cooperatively run lane-parallel occlusion (one lane
// per triangle, 3 segments) for each queued survivor, then write its output.
extern "C" __global__ void __launch_bounds__(BLOCK)
paths_kernel(const float* __restrict__ txs,
             const float* __restrict__ rxs,
             const float* __restrict__ vertices,
             const float* __restrict__ normals,
             const int*   __restrict__ tris,
             const int*   __restrict__ pc,
             float*       __restrict__ out,
             int P, int ntx, int nrx, int T)
{
    extern __shared__ float smem[];
    float* s_tv = smem;                 // T*9 : triangle vertices [t][vtx][xyz]
    float* s_pp = smem + T * 9;         // BLOCK*6 : p0,p1 per surviving thread
    __shared__ int s_q[BLOCK];          // queue of surviving local tids
    __shared__ int s_qc;                // queue count

    // Cooperative gather of triangle vertices into shared memory.
    for (int i = threadIdx.x; i < T * 9; i += blockDim.x) {
        int t = i / 9;
        int r = i - t * 9;              // 0..8
        int vi = tris[t * 3 + (r / 3)];
        s_tv[i] = vertices[vi * 3 + (r % 3)];
    }
    if (threadIdx.x == 0) s_qc = 0;
    __syncthreads();

    const int nwork = P * ntx * nrx;
    const int cand  = blockIdx.x * BLOCK + threadIdx.x;

    // ---------------- Phase A: per-thread path math ----------------
    if (cand < nwork) {
        // cand = (p*ntx + itx)*nrx + irx
        const int irx = cand % nrx;
        const int t1  = cand / nrx;
        const int itx = t1 % ntx;
        const int p   = t1 / ntx;

        const int c0 = pc[p * 2 + 0];
        const int c1 = pc[p * 2 + 1];

        const float3 tx = ldg3(txs + itx * 3);
        const float3 rx = ldg3(rxs + irx * 3);

        const float* ta = &s_tv[c0 * 9];
        const float* tb = &s_tv[c1 * 9];
        const float3 a0 = f3(ta[0], ta[1], ta[2]);
        const float3 a1 = f3(ta[3], ta[4], ta[5]);
        const float3 a2 = f3(ta[6], ta[7], ta[8]);
        const float3 b0 = f3(tb[0], tb[1], tb[2]);
        const float3 b1 = f3(tb[3], tb[4], tb[5]);
        const float3 b2 = f3(tb[6], tb[7], tb[8]);
        const float3 n0 = ldg3(normals + c0 * 3);
        const float3 n1 = ldg3(normals + c1 * 3);

        // image method (order = 2)
        float3 img0 = f3sub(tx,   f3scale(2.0f * dot3(f3sub(tx,   a0), n0), n0));
        float3 img1 = f3sub(img0, f3scale(2.0f * dot3(f3sub(img0, b0), n1), n1));

        // backward pass: i = 1
        float3 dvec = f3sub(rx, img1);
        float  den  = dot3(dvec, n1);
        float  tt   = dot3(f3sub(b0, img1), n1) / ((fabsf(den) < EPSF) ? EPSF : den);
        float3 p1   = f3add(img1, f3scale(tt, dvec));
        // i = 0
        dvec = f3sub(p1, img0);
        den  = dot3(dvec, n0);
        tt   = dot3(f3sub(a0, img0), n0) / ((fabsf(den) < EPSF) ? EPSF : den);
        float3 p0 = f3add(img0, f3scale(tt, dvec));

        // containment + same-side masks
        bool mask = tri_contains(a0, a1, a2, p0) && tri_contains(b0, b1, b2, p1);
        mask = mask && (dot3(f3sub(tx, a0), n0) * dot3(f3sub(p1, a0), n0) >= 0.0f);
        mask = mask && (dot3(f3sub(p0, b0), n1) * dot3(f3sub(rx, b0), n1) >= 0.0f);

        if (mask) {
            float* sp = &s_pp[threadIdx.x * 6];
            sp[0] = p0.x; sp[1] = p0.y; sp[2] = p0.z;
            sp[3] = p1.x; sp[4] = p1.y; sp[5] = p1.z;
            int slot = atomicAdd(&s_qc, 1);
            s_q[slot] = threadIdx.x;
        } else {
            // mask-fail: output zeros now
            float4* o4 = reinterpret_cast<float4*>(out + (size_t)cand * 12);
            const float4 z = make_float4(0.0f, 0.0f, 0.0f, 0.0f);
            o4[0] = z; o4[1] = z; o4[2] = z;
        }
    }
    __syncthreads();

    // ---------------- Phase B: warp-cooperative occlusion ----------------
    const int lane = threadIdx.x & 31;
    const int w    = threadIdx.x >> 5;
    const int nw   = BLOCK >> 5;
    const int qc   = s_qc;

    for (int q = w; q < qc; q += nw) {
        const int l = s_q[q];
        const int c = blockIdx.x * BLOCK + l;

        const int irx = c % nrx;
        const int t1  = c / nrx;
        const int itx = t1 % ntx;

        const float3 tx = ldg3(txs + itx * 3);
        const float3 rx = ldg3(rxs + irx * 3);
        const float* sp = &s_pp[l * 6];
        const float3 p0 = f3(sp[0], sp[1], sp[2]);
        const float3 p1 = f3(sp[3], sp[4], sp[5]);

        const float3 so[3] = { tx, p0, p1 };
        const float3 sd[3] = { f3sub(p0, tx), f3sub(p1, p0), f3sub(rx, p1) };

        bool occluded = false;
        for (int base = 0; base < T; base += 32) {
            const int tri = base + lane;
            bool local = false;
            if (tri < T) {
                const float* tp = &s_tv[tri * 9];
                const float3 v0 = f3(tp[0], tp[1], tp[2]);
                const float3 e1 = f3(tp[3] - tp[0], tp[4] - tp[1], tp[5] - tp[2]);
                const float3 e2 = f3(tp[6] - tp[0], tp[7] - tp[1], tp[8] - tp[2]);
                #pragma unroll
                for (int s = 0; s < 3; s++) {
                    const float3 h = cross3(sd[s], e2);
                    const float  a = dot3(e1, h);
                    const float  inv = 1.0f / ((fabsf(a) < EPSF) ? 1.0f : a);
                    const float3 sv = f3sub(so[s], v0);
                    const float  u  = dot3(sv, h) * inv;
                    const float3 qv = cross3(sv, e1);
                    const float  v  = dot3(sd[s], qv) * inv;
                    const float  th = dot3(e2, qv) * inv;
                    const bool hit = (fabsf(a) > EPSF) && (u >= 0.0f) && (v >= 0.0f) &&
                                     (u + v <= 1.0f) && (th > EPSF);
                    local |= hit && (th < TMAXF);
                }
            }
            if (__any_sync(0xFFFFFFFFu, local)) { occluded = true; break; }
        }

        if (lane == 0) {
            float4* o4 = reinterpret_cast<float4*>(out + (size_t)c * 12);
            if (!occluded) {
                o4[0] = make_float4(tx.x, tx.y, tx.z, p0.x);
                o4[1] = make_float4(p0.y, p0.z, p1.x, p1.y);
                o4[2] = make_float4(p1.z, rx.x, rx.y, rx.z);
            } else {
                const float4 z = make_float4(0.0f, 0.0f, 0.0f, 0.0f);
                o4[0] = z; o4[1] = z; o4[2] = z;
            }
        }
    }
}

extern "C" void kernel_launch(void* const* d_in, const int* in_sizes, int n_in,
                              void* d_out, int out_size)
{
    const float* txs      = (const float*)d_in[0];  // [ntx,3]
    const float* rxs      = (const float*)d_in[1];  // [nrx,3]
    const float* vertices = (const float*)d_in[2];  // [V,3]
    const float* normals  = (const float*)d_in[3];  // [T,3]
    const int*   tris     = (const int*)  d_in[4];  // [T,3]
    const int*   pc       = (const int*)  d_in[5];  // [P,2]  (order = 2)
    float*       out      = (float*)d_out;          // [P,ntx,nrx,4,3]

    const int ntx = in_sizes[0] / 3;
    const int nrx = in_sizes[1] / 3;
    const int T   = in_sizes[4] / 3;
    const int P   = in_sizes[5] / 2;

    const int nwork  = P * ntx * nrx;
    const int blocks = (nwork + BLOCK - 1) / BLOCK;
    const size_t smem = (size_t)(T * 9 + BLOCK * 6) * sizeof(float);

    paths_kernel<<<blocks, BLOCK, smem>>>(txs, rxs, vertices, normals, tris, pc,
                                          out, P, ntx, nrx, T);
}

// round 10
// speedup vs baseline: 1.0030x; 1.0030x over previous
#include <cuda_runtime.h>
#include <cuda_bf16.h>
#include <cstdint>

#define EPSF   1e-6f
#define TMAXF  0.999f

// ---------- small float3 helpers ----------
__device__ __forceinline__ float3 f3(float x, float y, float z) { return make_float3(x, y, z); }
__device__ __forceinline__ float3 f3sub(float3 a, float3 b) { return f3(a.x - b.x, a.y - b.y, a.z - b.z); }
__device__ __forceinline__ float3 f3add(float3 a, float3 b) { return f3(a.x + b.x, a.y + b.y, a.z + b.z); }
__device__ __forceinline__ float3 f3scale(float s, float3 a) { return f3(s * a.x, s * a.y, s * a.z); }
__device__ __forceinline__ float  dot3(float3 a, float3 b) { return a.x * b.x + a.y * b.y + a.z * b.z; }
__device__ __forceinline__ float3 cross3(float3 a, float3 b) {
    return f3(a.y * b.z - a.z * b.y,
              a.z * b.x - a.x * b.z,
              a.x * b.y - a.y * b.x);
}
__device__ __forceinline__ float3 ldg3(const float* __restrict__ p) {
    return f3(p[0], p[1], p[2]);
}

// triangles_contain (reference formula, fp32)
__device__ __forceinline__ bool tri_contains(float3 v0, float3 v1, float3 v2, float3 p) {
    float3 m0 = cross3(f3sub(p, v0), f3sub(v1, v0));
    float3 m1 = cross3(f3sub(p, v1), f3sub(v2, v1));
    float3 m2 = cross3(f3sub(p, v2), f3sub(v0, v2));
    float d01 = dot3(m0, m1);
    float d12 = dot3(m1, m2);
    float d20 = dot3(m2, m0);
    bool pos = (d01 >= 0.0f) && (d12 >= 0.0f) && (d20 >= 0.0f);
    bool neg = (d01 <= 0.0f) && (d12 <= 0.0f) && (d20 <= 0.0f);
    return pos || neg;
}

#define BLOCK 128

// Phase A: one THREAD per candidate computes the image-method path + masks.
// Survivors are compacted into a per-block shared queue.
// Phase B: block's warps cooperatively run lane-parallel occlusion (one lane
// per triangle, 3 segments) for each queued survivor, then write its output.
extern "C" __global__ void __launch_bounds__(BLOCK)
paths_kernel(const float* __restrict__ txs,
             const float* __restrict__ rxs,
             const float* __restrict__ vertices,
             const float* __restrict__ normals,
             const int*   __restrict__ tris,
             const int*   __restrict__ pc,
             float*       __restrict__ out,
             int P, int ntx, int nrx, int T)
{
    extern __shared__ float smem[];
    float* s_tv = smem;                 // T*9 : triangle vertices [t][vtx][xyz]
    float* s_pp = smem + T * 9;         // BLOCK*6 : p0,p1 per surviving thread
    __shared__ int s_q[BLOCK];          // queue of surviving local tids
    __shared__ int s_qc;                // queue count

    // Cooperative gather of triangle vertices into shared memory.
    for (int i = threadIdx.x; i < T * 9; i += blockDim.x) {
        int t = i / 9;
        int r = i - t * 9;              // 0..8
        int vi = tris[t * 3 + (r / 3)];
        s_tv[i] = vertices[vi * 3 + (r % 3)];
    }
    if (threadIdx.x == 0) s_qc = 0;
    __syncthreads();

    const int nwork = P * ntx * nrx;
    const int cand  = blockIdx.x * BLOCK + threadIdx.x;

    // ---------------- Phase A: per-thread path math ----------------
    if (cand < nwork) {
        // cand = (p*ntx + itx)*nrx + irx
        const int irx = cand % nrx;
        const int t1  = cand / nrx;
        const int itx = t1 % ntx;
        const int p   = t1 / ntx;

        const int c0 = pc[p * 2 + 0];
        const int c1 = pc[p * 2 + 1];

        const float3 tx = ldg3(txs + itx * 3);
        const float3 rx = ldg3(rxs + irx * 3);

        const float* ta = &s_tv[c0 * 9];
        const float* tb = &s_tv[c1 * 9];
        const float3 a0 = f3(ta[0], ta[1], ta[2]);
        const float3 a1 = f3(ta[3], ta[4], ta[5]);
        const float3 a2 = f3(ta[6], ta[7], ta[8]);
        const float3 b0 = f3(tb[0], tb[1], tb[2]);
        const float3 b1 = f3(tb[3], tb[4], tb[5]);
        const float3 b2 = f3(tb[6], tb[7], tb[8]);
        const float3 n0 = ldg3(normals + c0 * 3);
        const float3 n1 = ldg3(normals + c1 * 3);

        // image method (order = 2)
        float3 img0 = f3sub(tx,   f3scale(2.0f * dot3(f3sub(tx,   a0), n0), n0));
        float3 img1 = f3sub(img0, f3scale(2.0f * dot3(f3sub(img0, b0), n1), n1));

        // backward pass: i = 1
        float3 dvec = f3sub(rx, img1);
        float  den  = dot3(dvec, n1);
        float  tt   = dot3(f3sub(b0, img1), n1) / ((fabsf(den) < EPSF) ? EPSF : den);
        float3 p1   = f3add(img1, f3scale(tt, dvec));
        // i = 0
        dvec = f3sub(p1, img0);
        den  = dot3(dvec, n0);
        tt   = dot3(f3sub(a0, img0), n0) / ((fabsf(den) < EPSF) ? EPSF : den);
        float3 p0 = f3add(img0, f3scale(tt, dvec));

        // containment + same-side masks
        bool mask = tri_contains(a0, a1, a2, p0) && tri_contains(b0, b1, b2, p1);
        mask = mask && (dot3(f3sub(tx, a0), n0) * dot3(f3sub(p1, a0), n0) >= 0.0f);
        mask = mask && (dot3(f3sub(p0, b0), n1) * dot3(f3sub(rx, b0), n1) >= 0.0f);

        if (mask) {
            float* sp = &s_pp[threadIdx.x * 6];
            sp[0] = p0.x; sp[1] = p0.y; sp[2] = p0.z;
            sp[3] = p1.x; sp[4] = p1.y; sp[5] = p1.z;
            int slot = atomicAdd(&s_qc, 1);
            s_q[slot] = threadIdx.x;
        } else {
            // mask-fail: output zeros now
            float4* o4 = reinterpret_cast<float4*>(out + (size_t)cand * 12);
            const float4 z = make_float4(0.0f, 0.0f, 0.0f, 0.0f);
            o4[0] = z; o4[1] = z; o4[2] = z;
        }
    }
    __syncthreads();

    // ---------------- Phase B: warp-cooperative occlusion ----------------
    const int lane = threadIdx.x & 31;
    const int w    = threadIdx.x >> 5;
    const int nw   = BLOCK >> 5;
    const int qc   = s_qc;

    for (int q = w; q < qc; q += nw) {
        const int l = s_q[q];
        const int c = blockIdx.x * BLOCK + l;

        const int irx = c % nrx;
        const int t1  = c / nrx;
        const int itx = t1 % ntx;

        const float3 tx = ldg3(txs + itx * 3);
        const float3 rx = ldg3(rxs + irx * 3);
        const float* sp = &s_pp[l * 6];
        const float3 p0 = f3(sp[0], sp[1], sp[2]);
        const float3 p1 = f3(sp[3], sp[4], sp[5]);

        const float3 so[3] = { tx, p0, p1 };
        const float3 sd[3] = { f3sub(p0, tx), f3sub(p1, p0), f3sub(rx, p1) };

        bool occluded = false;
        for (int base = 0; base < T; base += 32) {
            const int tri = base + lane;
            bool local = false;
            if (tri < T) {
                const float* tp = &s_tv[tri * 9];
                const float3 v0 = f3(tp[0], tp[1], tp[2]);
                const float3 e1 = f3(tp[3] - tp[0], tp[4] - tp[1], tp[5] - tp[2]);
                const float3 e2 = f3(tp[6] - tp[0], tp[7] - tp[1], tp[8] - tp[2]);
                #pragma unroll
                for (int s = 0; s < 3; s++) {
                    const float3 h = cross3(sd[s], e2);
                    const float  a = dot3(e1, h);
                    const float  inv = 1.0f / ((fabsf(a) < EPSF) ? 1.0f : a);
                    const float3 sv = f3sub(so[s], v0);
                    const float  u  = dot3(sv, h) * inv;
                    const float3 qv = cross3(sv, e1);
                    const float  v  = dot3(sd[s], qv) * inv;
                    const float  th = dot3(e2, qv) * inv;
                    const bool hit = (fabsf(a) > EPSF) && (u >= 0.0f) && (v >= 0.0f) &&
                                     (u + v <= 1.0f) && (th > EPSF);
                    local |= hit && (th < TMAXF);
                }
            }
            if (__any_sync(0xFFFFFFFFu, local)) { occluded = true; break; }
        }

        if (lane == 0) {
            float4* o4 = reinterpret_cast<float4*>(out + (size_t)c * 12);
            if (!occluded) {
                o4[0] = make_float4(tx.x, tx.y, tx.z, p0.x);
                o4[1] = make_float4(p0.y, p0.z, p1.x, p1.y);
                o4[2] = make_float4(p1.z, rx.x, rx.y, rx.z);
            } else {
                const float4 z = make_float4(0.0f, 0.0f, 0.0f, 0.0f);
                o4[0] = z; o4[1] = z; o4[2] = z;
            }
        }
    }
}

extern "C" void kernel_launch(void* const* d_in, const int* in_sizes, int n_in,
                              void* d_out, int out_size)
{
    const float* txs      = (const float*)d_in[0];  // [ntx,3]
    const float* rxs      = (const float*)d_in[1];  // [nrx,3]
    const float* vertices = (const float*)d_in[2];  // [V,3]
    const float* normals  = (const float*)d_in[3];  // [T,3]
    const int*   tris     = (const int*)  d_in[4];  // [T,3]
    const int*   pc       = (const int*)  d_in[5];  // [P,2]  (order = 2)
    float*       out      = (float*)d_out;          // [P,ntx,nrx,4,3]

    const int ntx = in_sizes[0] / 3;
    const int nrx = in_sizes[1] / 3;
    const int T   = in_sizes[4] / 3;
    const int P   = in_sizes[5] / 2;

    const int nwork  = P * ntx * nrx;
    const int blocks = (nwork + BLOCK - 1) / BLOCK;
    const size_t smem = (size_t)(T * 9 + BLOCK * 6) * sizeof(float);

    paths_kernel<<<blocks, BLOCK, smem>>>(txs, rxs, vertices, normals, tris, pc,
                                          out, P, ntx, nrx, T);
}